// round 14
// baseline (speedup 1.0000x reference)
#include <cuda_runtime.h>
#include <cuda_fp16.h>
#include <cstdint>
#include <math.h>

#define Bz 128
#define Hz 512
#define Nz 1024

// ---------------- scratch (no allocs allowed) ----------------
__device__ float g_mcproj[Bz * Hz];
__device__ float g_scores[Bz * Nz];   // scores, then attns in-place
__device__ float g_context[Bz * Hz];
__device__ float g_out[Bz * Hz];
__device__ __half g_Wh[Hz * Hz];                // attn_W[:, :H] fp16
__device__ __half g_snh[(size_t)Bz * Hz * Nz];  // sn fp16 (134MB)

__device__ __forceinline__ uint32_t smem_u32(const void* p) {
    uint32_t a;
    asm("{ .reg .u64 t; cvta.to.shared.u64 t, %1; cvt.u32.u64 %0, t; }"
        : "=r"(a) : "l"(p));
    return a;
}
// HW tanh f16x2: ONE MUFU op evaluates TWO tanh
__device__ __forceinline__ uint32_t tanh_h2(uint32_t x) {
    uint32_t y;
    asm("tanh.approx.f16x2 %0, %1;" : "=r"(y) : "r"(x));
    return y;
}
// pack two fp32 -> f16x2 (single cvt op)
__device__ __forceinline__ uint32_t pack_h2(float lo, float hi) {
    uint32_t p;
    asm("cvt.rn.f16x2.f32 %0, %1, %2;" : "=r"(p) : "f"(hi), "f"(lo));
    return p;
}

// ldmatrix x4 (row-major fragments)
__device__ __forceinline__ void ldsm_x4(uint32_t* r, uint32_t addr) {
    asm volatile("ldmatrix.sync.aligned.m8n8.x4.shared.b16 {%0,%1,%2,%3}, [%4];"
                 : "=r"(r[0]), "=r"(r[1]), "=r"(r[2]), "=r"(r[3]) : "r"(addr));
}
// ldmatrix x4 transposed (col-major B fragments)
__device__ __forceinline__ void ldsm_x4_t(uint32_t* r, uint32_t addr) {
    asm volatile("ldmatrix.sync.aligned.m8n8.x4.trans.shared.b16 {%0,%1,%2,%3}, [%4];"
                 : "=r"(r[0]), "=r"(r[1]), "=r"(r[2]), "=r"(r[3]) : "r"(addr));
}
// D += A * B  (m16n8k16, fp16 in, fp32 acc)
__device__ __forceinline__ void mma16816(float* c, const uint32_t* a, const uint32_t* b) {
    asm volatile("mma.sync.aligned.m16n8k16.row.col.f32.f16.f16.f32 "
                 "{%0,%1,%2,%3}, {%4,%5,%6,%7}, {%8,%9}, {%0,%1,%2,%3};"
                 : "+f"(c[0]), "+f"(c[1]), "+f"(c[2]), "+f"(c[3])
                 : "r"(a[0]), "r"(a[1]), "r"(a[2]), "r"(a[3]), "r"(b[0]), "r"(b[1]));
}
__device__ __forceinline__ void cp16(uint32_t dst, const void* src) {
    size_t g = __cvta_generic_to_global(src);
    asm volatile("cp.async.cg.shared.global [%0], [%1], 16;" :: "r"(dst), "l"(g));
}
#define CP_COMMIT() asm volatile("cp.async.commit_group;" ::: "memory")
#define CP_WAIT(n)  asm volatile("cp.async.wait_group %0;" :: "n"(n) : "memory")

// ============================================================
// Kernel P1: convert attn_W[:, :H] to fp16
// ============================================================
__global__ __launch_bounds__(256) void wconv_kernel(const float* __restrict__ W)
{
    int i = blockIdx.x * 256 + threadIdx.x;   // over Hz*Hz
    int h = i >> 9, k = i & 511;
    g_Wh[i] = __float2half_rn(W[h * (2 * Hz) + k]);
}

// ============================================================
// Kernel P2: convert sn to fp16 (linear, float4 per thread)
// ============================================================
__global__ __launch_bounds__(256) void snconv_kernel(const float* __restrict__ sn)
{
    size_t i = (size_t)blockIdx.x * 256 + threadIdx.x;   // over total/4
    float4 x = ((const float4*)sn)[i];
    uint2 o;
    o.x = pack_h2(x.x, x.y);
    o.y = pack_h2(x.z, x.w);
    ((uint2*)g_snh)[i] = o;
}

// ============================================================
// Kernel A: mcproj[b,h] = sum_k attn_W[h, H+k] * mc[b,k]
// ============================================================
__global__ __launch_bounds__(256) void mcproj_kernel(
    const float* __restrict__ mc, const float* __restrict__ W)
{
    __shared__ float s_mc[4][Hz];
    int b0 = blockIdx.x * 4;
    for (int i = threadIdx.x; i < 4 * Hz; i += 256)
        s_mc[i >> 9][i & 511] = mc[(b0 + (i >> 9)) * Hz + (i & 511)];
    __syncthreads();

    int warp = threadIdx.x >> 5, lane = threadIdx.x & 31;
    for (int h = warp; h < Hz; h += 8) {
        const float* wr = W + h * (2 * Hz) + Hz;
        float a0 = 0.f, a1 = 0.f, a2 = 0.f, a3 = 0.f;
        for (int k = lane; k < Hz; k += 32) {
            float w = wr[k];
            a0 += w * s_mc[0][k];
            a1 += w * s_mc[1][k];
            a2 += w * s_mc[2][k];
            a3 += w * s_mc[3][k];
        }
        #pragma unroll
        for (int off = 16; off; off >>= 1) {
            a0 += __shfl_xor_sync(0xffffffffu, a0, off);
            a1 += __shfl_xor_sync(0xffffffffu, a1, off);
            a2 += __shfl_xor_sync(0xffffffffu, a2, off);
            a3 += __shfl_xor_sync(0xffffffffu, a3, off);
        }
        if (lane == 0) {
            g_mcproj[(b0 + 0) * Hz + h] = a0;
            g_mcproj[(b0 + 1) * Hz + h] = a1;
            g_mcproj[(b0 + 2) * Hz + h] = a2;
            g_mcproj[(b0 + 3) * Hz + h] = a3;
        }
    }
}

// ============================================================
// Kernel B (HMMA + 3-stage cp.async): scores[b,n]
//   = sum_h v[h]*tanh(mc[b,h] + sum_k W[h,k]*sn[b,k,n])
// grid (8 n-strips, 128 b), 512 thr = 16 warps (8h x 2n),
// warp tile 32h x 64n. Single fp16 product.
// 2 h-passes of 256h; k in 64-chunks, 3 smem slots, 1 sync/chunk.
// Epilogue tanh via f16x2 MUFU (half the MUFU ops).
// ============================================================
static constexpr int PA = 72;    // A pitch (ushorts) = 144B (odd 16B groups)
static constexpr int PB = 136;   // B pitch (ushorts) = 272B (odd 16B groups)
static constexpr int A_SZ = 256 * PA * 2;     // 36864 B (256h x 64k)
static constexpr int B_SZ = 64 * PB * 2;      // 17408 B (64k x 128n)
static constexpr int SLOT_SZ = A_SZ + B_SZ;   // 54272 B
static constexpr int OFF_PART = 3 * SLOT_SZ;              // 162816 (8x128 fl)
static constexpr int OFF_MC   = OFF_PART + 1024 * 4;      // 166912
static constexpr int OFF_V    = OFF_MC + Hz * 4;          // 168960
static constexpr int SCORE_SMEM = OFF_V + Hz * 4;         // 171008

__device__ __forceinline__ void prefetch_chunk(
    uint32_t slotbase, int h0, int k0, int b, int n0, int tid)
{
    // A: 256h x 64k fp16 = 2048 x 16B, 4 per thread
    #pragma unroll
    for (int it = 0; it < 4; it++) {
        int i = tid + it * 512;           // 0..2047
        int h = i >> 3, ch = i & 7;
        uint32_t dst = slotbase + h * (PA * 2) + ch * 16;
        size_t off = (size_t)(h0 + h) * Hz + k0 + ch * 8;
        cp16(dst, g_Wh + off);
    }
    // B: 64k x 128n fp16 = 1024 x 16B, 2 per thread
    uint32_t Bb = slotbase + A_SZ;
    #pragma unroll
    for (int it = 0; it < 2; it++) {
        int i = tid + it * 512;           // 0..1023
        int k = i >> 4, ch = i & 15;
        uint32_t dst = Bb + k * (PB * 2) + ch * 16;
        size_t off = ((size_t)b * Hz + k0 + k) * Nz + n0 + ch * 8;
        cp16(dst, g_snh + off);
    }
}

__global__ __launch_bounds__(512, 1) void score_mma_kernel(const float* __restrict__ v)
{
    extern __shared__ char smem[];
    uint32_t sb = smem_u32(smem);
    int tid = threadIdx.x, w = tid >> 5, lane = tid & 31;
    int wh = w >> 1, wn = w & 1;          // 8 h-warps x 2 n-warps
    int b = blockIdx.y, n0 = blockIdx.x * 128;

    float* s_part = (float*)(smem + OFF_PART);
    float* s_mc   = (float*)(smem + OFF_MC);
    float* s_v    = (float*)(smem + OFF_V);
    for (int i = tid; i < Hz; i += 512) {
        s_mc[i] = g_mcproj[b * Hz + i];
        s_v[i]  = v[i];
    }
    for (int i = tid; i < 1024; i += 512) s_part[i] = 0.f;
    __syncthreads();

    int lrow = lane & 15, lcol8 = (lane >> 4) << 3;
    uint32_t aBase = sb + ((wh * 32 + lrow) * PA + lcol8) * 2;
    uint32_t bBase = sb + A_SZ + (lrow * PB + wn * 64 + lcol8) * 2;
    int g = lane >> 2, c = lane & 3;

    for (int pass = 0; pass < 2; pass++) {
        int h0 = pass * 256;
        float acc[2][8][4];
        #pragma unroll
        for (int mi = 0; mi < 2; mi++)
            #pragma unroll
            for (int j = 0; j < 8; j++)
                #pragma unroll
                for (int r = 0; r < 4; r++) acc[mi][j][r] = 0.f;

        // pipeline init: chunks 0,1 -> slots 0,1
        prefetch_chunk(sb + 0 * SLOT_SZ, h0, 0, b, n0, tid);
        CP_COMMIT();
        prefetch_chunk(sb + 1 * SLOT_SZ, h0, 64, b, n0, tid);
        CP_COMMIT();

        int slot = 0;
        for (int kc = 0; kc < 8; kc++) {
            if (kc < 7) { CP_WAIT(1); } else { CP_WAIT(0); }
            __syncthreads();   // data visible + slot (kc+2)%3 free of readers
            if (kc < 6) {
                int ps = (kc + 2) % 3;
                prefetch_chunk(sb + ps * SLOT_SZ, h0, (kc + 2) * 64, b, n0, tid);
                CP_COMMIT();
            }
            uint32_t so = (uint32_t)(slot * SLOT_SZ);
            #pragma unroll
            for (int ks = 0; ks < 4; ks++) {
                uint32_t a[2][4];
                #pragma unroll
                for (int mi = 0; mi < 2; mi++)
                    ldsm_x4(a[mi], aBase + so + (uint32_t)((mi * 16 * PA + ks * 16) * 2));
                #pragma unroll
                for (int np = 0; np < 4; np++) {
                    uint32_t bb[4];
                    ldsm_x4_t(bb, bBase + so + (uint32_t)((ks * 16 * PB + np * 16) * 2));
                    #pragma unroll
                    for (int mi = 0; mi < 2; mi++) {
                        #pragma unroll
                        for (int q = 0; q < 2; q++)
                            mma16816(acc[mi][np * 2 + q], a[mi], bb + q * 2);
                    }
                }
            }
            slot = (slot + 1) % 3;
        }

        // ---- epilogue: v[h]*tanh(acc + mc[h]) via f16x2 tanh; shfl-reduce ----
        int hb = h0 + wh * 32;
        float v0 = s_v[hb + g],      m0 = s_mc[hb + g];
        float v1 = s_v[hb + g + 8],  m1 = s_mc[hb + g + 8];
        float v2 = s_v[hb + g + 16], m2 = s_mc[hb + g + 16];
        float v3 = s_v[hb + g + 24], m3 = s_mc[hb + g + 24];
        #pragma unroll
        for (int j = 0; j < 8; j++) {
            #pragma unroll
            for (int p = 0; p < 2; p++) {
                uint32_t p01 = pack_h2(acc[0][j][p] + m0, acc[0][j][2 + p] + m1);
                uint32_t p23 = pack_h2(acc[1][j][p] + m2, acc[1][j][2 + p] + m3);
                float2 t01 = __half22float2(*(__half2*)&(uint32_t&)(p01 = tanh_h2(p01)));
                float2 t23 = __half22float2(*(__half2*)&(uint32_t&)(p23 = tanh_h2(p23)));
                float t = v0 * t01.x + v1 * t01.y + v2 * t23.x + v3 * t23.y;
                t += __shfl_xor_sync(0xffffffffu, t, 4);
                t += __shfl_xor_sync(0xffffffffu, t, 8);
                t += __shfl_xor_sync(0xffffffffu, t, 16);
                if (g == 0)
                    s_part[wh * 128 + wn * 64 + j * 8 + c * 2 + p] += t;
            }
        }
        __syncthreads();   // all MMA/epilogue reads done before next pass prefetch
    }

    if (tid < 128) {
        float s = 0.f;
        #pragma unroll
        for (int ww = 0; ww < 8; ww++) s += s_part[ww * 128 + tid];
        g_scores[b * Nz + n0 + tid] = s;
    }
}

// ============================================================
// Kernel C: row softmax over scores (in-place -> attns)
// ============================================================
__global__ __launch_bounds__(256) void softmax_kernel()
{
    __shared__ float s_red[8];
    int b = blockIdx.x, tid = threadIdx.x;
    int warp = tid >> 5, lane = tid & 31;

    float4 vv = *(const float4*)&g_scores[b * Nz + tid * 4];
    float m = fmaxf(fmaxf(vv.x, vv.y), fmaxf(vv.z, vv.w));
    #pragma unroll
    for (int off = 16; off; off >>= 1)
        m = fmaxf(m, __shfl_xor_sync(0xffffffffu, m, off));
    if (lane == 0) s_red[warp] = m;
    __syncthreads();
    m = s_red[0];
    #pragma unroll
    for (int w = 1; w < 8; w++) m = fmaxf(m, s_red[w]);
    __syncthreads();

    float e0 = expf(vv.x - m), e1 = expf(vv.y - m);
    float e2 = expf(vv.z - m), e3 = expf(vv.w - m);
    float s = e0 + e1 + e2 + e3;
    #pragma unroll
    for (int off = 16; off; off >>= 1)
        s += __shfl_xor_sync(0xffffffffu, s, off);
    if (lane == 0) s_red[warp] = s;
    __syncthreads();
    float tot = 0.f;
    #pragma unroll
    for (int w = 0; w < 8; w++) tot += s_red[w];
    float inv = 1.0f / tot;

    float4 o = make_float4(e0 * inv, e1 * inv, e2 * inv, e3 * inv);
    *(float4*)&g_scores[b * Nz + tid * 4] = o;
}

// ============================================================
// Kernel D: context[b,h] = sum_n attn[b,n]*sn[b,h,n]  (fp16 sn)
// ============================================================
__global__ __launch_bounds__(256) void context_kernel()
{
    __shared__ float s_a[Nz];
    int b = blockIdx.y, h0 = blockIdx.x * 64;
    int tid = threadIdx.x;
    for (int i = tid; i < Nz; i += 256) s_a[i] = g_scores[b * Nz + i];
    __syncthreads();

    int warp = tid >> 5, lane = tid & 31;
    for (int h = h0 + warp; h < h0 + 64; h += 8) {
        const uint4* row = (const uint4*)(g_snh + ((size_t)b * Hz + h) * Nz);
        float a = 0.f;
        #pragma unroll 4
        for (int i = lane; i < Nz / 8; i += 32) {
            uint4 x = row[i];
            const __half2* hp = (const __half2*)&x;
            const float* aw = s_a + i * 8;
            float2 f0 = __half22float2(hp[0]);
            float2 f1 = __half22float2(hp[1]);
            float2 f2 = __half22float2(hp[2]);
            float2 f3 = __half22float2(hp[3]);
            a += f0.x * aw[0] + f0.y * aw[1] + f1.x * aw[2] + f1.y * aw[3]
               + f2.x * aw[4] + f2.y * aw[5] + f3.x * aw[6] + f3.y * aw[7];
        }
        #pragma unroll
        for (int off = 16; off; off >>= 1)
            a += __shfl_xor_sync(0xffffffffu, a, off);
        if (lane == 0) g_context[b * Hz + h] = a;
    }
}

// ============================================================
// Kernel E: out = relu(relu([mc,context]@fc1_W^T + b1)@fc2_W^T + b2)
// ============================================================
__global__ __launch_bounds__(256) void fc_kernel(
    const float* __restrict__ mc,
    const float* __restrict__ fc1W, const float* __restrict__ fc1b,
    const float* __restrict__ fc2W, const float* __restrict__ fc2b)
{
    __shared__ float s_x[4][2 * Hz];
    __shared__ float s_o1[4][Hz];
    int b0 = blockIdx.x * 4;
    int tid = threadIdx.x;

    for (int i = tid; i < 4 * Hz; i += 256) {
        int bb = i >> 9, j = i & 511;
        s_x[bb][j]      = mc[(b0 + bb) * Hz + j];
        s_x[bb][Hz + j] = g_context[(b0 + bb) * Hz + j];
    }
    __syncthreads();

    int warp = tid >> 5, lane = tid & 31;
    for (int h = warp; h < Hz; h += 8) {
        const float* wr = fc1W + h * (2 * Hz);
        float a0 = 0.f, a1 = 0.f, a2 = 0.f, a3 = 0.f;
        for (int k = lane; k < 2 * Hz; k += 32) {
            float w = wr[k];
            a0 += w * s_x[0][k]; a1 += w * s_x[1][k];
            a2 += w * s_x[2][k]; a3 += w * s_x[3][k];
        }
        #pragma unroll
        for (int off = 16; off; off >>= 1) {
            a0 += __shfl_xor_sync(0xffffffffu, a0, off);
            a1 += __shfl_xor_sync(0xffffffffu, a1, off);
            a2 += __shfl_xor_sync(0xffffffffu, a2, off);
            a3 += __shfl_xor_sync(0xffffffffu, a3, off);
        }
        if (lane == 0) {
            float bb = fc1b[h];
            s_o1[0][h] = fmaxf(a0 + bb, 0.f);
            s_o1[1][h] = fmaxf(a1 + bb, 0.f);
            s_o1[2][h] = fmaxf(a2 + bb, 0.f);
            s_o1[3][h] = fmaxf(a3 + bb, 0.f);
        }
    }
    __syncthreads();
    for (int h = warp; h < Hz; h += 8) {
        const float* wr = fc2W + h * Hz;
        float a0 = 0.f, a1 = 0.f, a2 = 0.f, a3 = 0.f;
        for (int k = lane; k < Hz; k += 32) {
            float w = wr[k];
            a0 += w * s_o1[0][k]; a1 += w * s_o1[1][k];
            a2 += w * s_o1[2][k]; a3 += w * s_o1[3][k];
        }
        #pragma unroll
        for (int off = 16; off; off >>= 1) {
            a0 += __shfl_xor_sync(0xffffffffu, a0, off);
            a1 += __shfl_xor_sync(0xffffffffu, a1, off);
            a2 += __shfl_xor_sync(0xffffffffu, a2, off);
            a3 += __shfl_xor_sync(0xffffffffu, a3, off);
        }
        if (lane == 0) {
            float bb = fc2b[h];
            g_out[(b0 + 0) * Hz + h] = fmaxf(a0 + bb, 0.f);
            g_out[(b0 + 1) * Hz + h] = fmaxf(a1 + bb, 0.f);
            g_out[(b0 + 2) * Hz + h] = fmaxf(a2 + bb, 0.f);
            g_out[(b0 + 3) * Hz + h] = fmaxf(a3 + bb, 0.f);
        }
    }
}

// ============================================================
// Kernel F: probs[b,n] = sum_h ptr_v[h]*tanh(sn[b,h,n] + out[b,h])
// fp16 sn; 2 n per thread; argument in fp32, ONE tanh.approx.f16x2
// per 2 elements (halves MUFU count vs f32 tanh).
// ============================================================
__global__ __launch_bounds__(256) void probs_kernel(
    const float* __restrict__ pv, float* __restrict__ out)
{
    __shared__ float s_o[Hz];
    __shared__ float s_v[Hz];
    int b = blockIdx.y;
    int n0 = blockIdx.x * 512 + threadIdx.x * 2;
    for (int i = threadIdx.x; i < Hz; i += 256) {
        s_o[i] = g_out[b * Hz + i];
        s_v[i] = pv[i];
    }
    __syncthreads();

    const __half* base = g_snh + (size_t)b * Hz * Nz + n0;
    float a0 = 0.f, a1 = 0.f;
    #pragma unroll 8
    for (int h = 0; h < Hz; h++) {
        uint32_t xp = *(const uint32_t*)(base + (size_t)h * Nz);
        float2 x = __half22float2(*(const __half2*)&xp);
        float o = s_o[h], vh = s_v[h];
        uint32_t t = tanh_h2(pack_h2(x.x + o, x.y + o));
        float2 tf = __half22float2(*(__half2*)&t);
        a0 += vh * tf.x;
        a1 += vh * tf.y;
    }
    float2 r = make_float2(a0, a1);
    *(float2*)&out[b * Nz + n0] = r;
}

// ============================================================
extern "C" void kernel_launch(void* const* d_in, const int* in_sizes, int n_in,
                              void* d_out, int out_size)
{
    const float* mc   = (const float*)d_in[0];
    const float* sn   = (const float*)d_in[1];
    const float* attW = (const float*)d_in[2];
    const float* attv = (const float*)d_in[3];
    const float* ptrv = (const float*)d_in[4];
    const float* fc1W = (const float*)d_in[5];
    const float* fc1b = (const float*)d_in[6];
    const float* fc2W = (const float*)d_in[7];
    const float* fc2b = (const float*)d_in[8];
    float* out = (float*)d_out;

    cudaFuncSetAttribute(score_mma_kernel,
                         cudaFuncAttributeMaxDynamicSharedMemorySize, SCORE_SMEM);

    wconv_kernel<<<Hz * Hz / 256, 256>>>(attW);
    snconv_kernel<<<(int)(((size_t)Bz * Hz * Nz / 4) / 256), 256>>>(sn);
    mcproj_kernel<<<Bz / 4, 256>>>(mc, attW);
    score_mma_kernel<<<dim3(8, Bz), 512, SCORE_SMEM>>>(attv);
    softmax_kernel<<<Bz, 256>>>();
    context_kernel<<<dim3(8, Bz), 256>>>();
    fc_kernel<<<Bz / 4, 256>>>(mc, fc1W, fc1b, fc2W, fc2b);
    probs_kernel<<<dim3(Nz / 512, Bz), 256>>>(ptrv, out);
}

// round 15
// speedup vs baseline: 1.3316x; 1.3316x over previous
#include <cuda_runtime.h>
#include <cuda_fp16.h>
#include <cstdint>
#include <math.h>

#define Bz 128
#define Hz 512
#define Nz 1024

// ---------------- scratch (no allocs allowed) ----------------
__device__ float g_mcproj[Bz * Hz];
__device__ float g_scores[Bz * Nz];   // scores, then attns in-place
__device__ float g_context[Bz * Hz];
__device__ float g_out[Bz * Hz];
__device__ __half g_Wh[Hz * Hz];                // attn_W[:, :H] fp16
__device__ __half g_snh[(size_t)Bz * Hz * Nz];  // sn fp16 (134MB)

__device__ __forceinline__ uint32_t smem_u32(const void* p) {
    uint32_t a;
    asm("{ .reg .u64 t; cvta.to.shared.u64 t, %1; cvt.u32.u64 %0, t; }"
        : "=r"(a) : "l"(p));
    return a;
}
// HW tanh f16x2: ONE MUFU op evaluates TWO tanh (for probs only)
__device__ __forceinline__ uint32_t tanh_h2(uint32_t x) {
    uint32_t y;
    asm("tanh.approx.f16x2 %0, %1;" : "=r"(y) : "r"(x));
    return y;
}
// pack two fp32 -> f16x2 (single cvt op)
__device__ __forceinline__ uint32_t pack_h2(float lo, float hi) {
    uint32_t p;
    asm("cvt.rn.f16x2.f32 %0, %1, %2;" : "=r"(p) : "f"(hi), "f"(lo));
    return p;
}

// ldmatrix x4 (row-major fragments)
__device__ __forceinline__ void ldsm_x4(uint32_t* r, uint32_t addr) {
    asm volatile("ldmatrix.sync.aligned.m8n8.x4.shared.b16 {%0,%1,%2,%3}, [%4];"
                 : "=r"(r[0]), "=r"(r[1]), "=r"(r[2]), "=r"(r[3]) : "r"(addr));
}
// ldmatrix x4 transposed (col-major B fragments)
__device__ __forceinline__ void ldsm_x4_t(uint32_t* r, uint32_t addr) {
    asm volatile("ldmatrix.sync.aligned.m8n8.x4.trans.shared.b16 {%0,%1,%2,%3}, [%4];"
                 : "=r"(r[0]), "=r"(r[1]), "=r"(r[2]), "=r"(r[3]) : "r"(addr));
}
// D += A * B  (m16n8k16, fp16 in, fp32 acc)
__device__ __forceinline__ void mma16816(float* c, const uint32_t* a, const uint32_t* b) {
    asm volatile("mma.sync.aligned.m16n8k16.row.col.f32.f16.f16.f32 "
                 "{%0,%1,%2,%3}, {%4,%5,%6,%7}, {%8,%9}, {%0,%1,%2,%3};"
                 : "+f"(c[0]), "+f"(c[1]), "+f"(c[2]), "+f"(c[3])
                 : "r"(a[0]), "r"(a[1]), "r"(a[2]), "r"(a[3]), "r"(b[0]), "r"(b[1]));
}
__device__ __forceinline__ void cp16(uint32_t dst, const void* src) {
    size_t g = __cvta_generic_to_global(src);
    asm volatile("cp.async.cg.shared.global [%0], [%1], 16;" :: "r"(dst), "l"(g));
}
#define CP_COMMIT() asm volatile("cp.async.commit_group;" ::: "memory")
#define CP_WAIT(n)  asm volatile("cp.async.wait_group %0;" :: "n"(n) : "memory")

// ============================================================
// Kernel P1: convert attn_W[:, :H] to fp16
// ============================================================
__global__ __launch_bounds__(256) void wconv_kernel(const float* __restrict__ W)
{
    int i = blockIdx.x * 256 + threadIdx.x;   // over Hz*Hz
    int h = i >> 9, k = i & 511;
    g_Wh[i] = __float2half_rn(W[h * (2 * Hz) + k]);
}

// ============================================================
// Kernel P2: convert sn to fp16 (linear, float4 per thread)
// ============================================================
__global__ __launch_bounds__(256) void snconv_kernel(const float* __restrict__ sn)
{
    size_t i = (size_t)blockIdx.x * 256 + threadIdx.x;   // over total/4
    float4 x = ((const float4*)sn)[i];
    uint2 o;
    o.x = pack_h2(x.x, x.y);
    o.y = pack_h2(x.z, x.w);
    ((uint2*)g_snh)[i] = o;
}

// ============================================================
// Kernel A: mcproj[b,h] = sum_k attn_W[h, H+k] * mc[b,k]
// ============================================================
__global__ __launch_bounds__(256) void mcproj_kernel(
    const float* __restrict__ mc, const float* __restrict__ W)
{
    __shared__ float s_mc[4][Hz];
    int b0 = blockIdx.x * 4;
    for (int i = threadIdx.x; i < 4 * Hz; i += 256)
        s_mc[i >> 9][i & 511] = mc[(b0 + (i >> 9)) * Hz + (i & 511)];
    __syncthreads();

    int warp = threadIdx.x >> 5, lane = threadIdx.x & 31;
    for (int h = warp; h < Hz; h += 8) {
        const float* wr = W + h * (2 * Hz) + Hz;
        float a0 = 0.f, a1 = 0.f, a2 = 0.f, a3 = 0.f;
        for (int k = lane; k < Hz; k += 32) {
            float w = wr[k];
            a0 += w * s_mc[0][k];
            a1 += w * s_mc[1][k];
            a2 += w * s_mc[2][k];
            a3 += w * s_mc[3][k];
        }
        #pragma unroll
        for (int off = 16; off; off >>= 1) {
            a0 += __shfl_xor_sync(0xffffffffu, a0, off);
            a1 += __shfl_xor_sync(0xffffffffu, a1, off);
            a2 += __shfl_xor_sync(0xffffffffu, a2, off);
            a3 += __shfl_xor_sync(0xffffffffu, a3, off);
        }
        if (lane == 0) {
            g_mcproj[(b0 + 0) * Hz + h] = a0;
            g_mcproj[(b0 + 1) * Hz + h] = a1;
            g_mcproj[(b0 + 2) * Hz + h] = a2;
            g_mcproj[(b0 + 3) * Hz + h] = a3;
        }
    }
}

// ============================================================
// Kernel B (HMMA + 3-stage cp.async): scores[b,n]
//   = sum_h v[h]*tanh(mc[b,h] + sum_k W[h,k]*sn[b,k,n])
// grid (8 n-strips, 128 b), 512 thr = 16 warps (8h x 2n),
// warp tile 32h x 64n. Single fp16 product.
// 2 h-passes of 256h; k in 64-chunks, 3 smem slots, 1 sync/chunk.
// Epilogue tanh via tanhf (FMA-pipe polynomial — measured fastest:
// the epilogue is a MUFU burst, polynomial spreads onto idle FMA pipe).
// ============================================================
static constexpr int PA = 72;    // A pitch (ushorts) = 144B (odd 16B groups)
static constexpr int PB = 136;   // B pitch (ushorts) = 272B (odd 16B groups)
static constexpr int A_SZ = 256 * PA * 2;     // 36864 B (256h x 64k)
static constexpr int B_SZ = 64 * PB * 2;      // 17408 B (64k x 128n)
static constexpr int SLOT_SZ = A_SZ + B_SZ;   // 54272 B
static constexpr int OFF_PART = 3 * SLOT_SZ;              // 162816 (8x128 fl)
static constexpr int OFF_MC   = OFF_PART + 1024 * 4;      // 166912
static constexpr int OFF_V    = OFF_MC + Hz * 4;          // 168960
static constexpr int SCORE_SMEM = OFF_V + Hz * 4;         // 171008

__device__ __forceinline__ void prefetch_chunk(
    uint32_t slotbase, int h0, int k0, int b, int n0, int tid)
{
    // A: 256h x 64k fp16 = 2048 x 16B, 4 per thread
    #pragma unroll
    for (int it = 0; it < 4; it++) {
        int i = tid + it * 512;           // 0..2047
        int h = i >> 3, ch = i & 7;
        uint32_t dst = slotbase + h * (PA * 2) + ch * 16;
        size_t off = (size_t)(h0 + h) * Hz + k0 + ch * 8;
        cp16(dst, g_Wh + off);
    }
    // B: 64k x 128n fp16 = 1024 x 16B, 2 per thread
    uint32_t Bb = slotbase + A_SZ;
    #pragma unroll
    for (int it = 0; it < 2; it++) {
        int i = tid + it * 512;           // 0..1023
        int k = i >> 4, ch = i & 15;
        uint32_t dst = Bb + k * (PB * 2) + ch * 16;
        size_t off = ((size_t)b * Hz + k0 + k) * Nz + n0 + ch * 8;
        cp16(dst, g_snh + off);
    }
}

__global__ __launch_bounds__(512, 1) void score_mma_kernel(const float* __restrict__ v)
{
    extern __shared__ char smem[];
    uint32_t sb = smem_u32(smem);
    int tid = threadIdx.x, w = tid >> 5, lane = tid & 31;
    int wh = w >> 1, wn = w & 1;          // 8 h-warps x 2 n-warps
    int b = blockIdx.y, n0 = blockIdx.x * 128;

    float* s_part = (float*)(smem + OFF_PART);
    float* s_mc   = (float*)(smem + OFF_MC);
    float* s_v    = (float*)(smem + OFF_V);
    for (int i = tid; i < Hz; i += 512) {
        s_mc[i] = g_mcproj[b * Hz + i];
        s_v[i]  = v[i];
    }
    for (int i = tid; i < 1024; i += 512) s_part[i] = 0.f;
    __syncthreads();

    int lrow = lane & 15, lcol8 = (lane >> 4) << 3;
    uint32_t aBase = sb + ((wh * 32 + lrow) * PA + lcol8) * 2;
    uint32_t bBase = sb + A_SZ + (lrow * PB + wn * 64 + lcol8) * 2;
    int g = lane >> 2, c = lane & 3;

    for (int pass = 0; pass < 2; pass++) {
        int h0 = pass * 256;
        float acc[2][8][4];
        #pragma unroll
        for (int mi = 0; mi < 2; mi++)
            #pragma unroll
            for (int j = 0; j < 8; j++)
                #pragma unroll
                for (int r = 0; r < 4; r++) acc[mi][j][r] = 0.f;

        // pipeline init: chunks 0,1 -> slots 0,1
        prefetch_chunk(sb + 0 * SLOT_SZ, h0, 0, b, n0, tid);
        CP_COMMIT();
        prefetch_chunk(sb + 1 * SLOT_SZ, h0, 64, b, n0, tid);
        CP_COMMIT();

        int slot = 0;
        for (int kc = 0; kc < 8; kc++) {
            if (kc < 7) { CP_WAIT(1); } else { CP_WAIT(0); }
            __syncthreads();   // data visible + slot (kc+2)%3 free of readers
            if (kc < 6) {
                int ps = (kc + 2) % 3;
                prefetch_chunk(sb + ps * SLOT_SZ, h0, (kc + 2) * 64, b, n0, tid);
                CP_COMMIT();
            }
            uint32_t so = (uint32_t)(slot * SLOT_SZ);
            #pragma unroll
            for (int ks = 0; ks < 4; ks++) {
                uint32_t a[2][4];
                #pragma unroll
                for (int mi = 0; mi < 2; mi++)
                    ldsm_x4(a[mi], aBase + so + (uint32_t)((mi * 16 * PA + ks * 16) * 2));
                #pragma unroll
                for (int np = 0; np < 4; np++) {
                    uint32_t bb[4];
                    ldsm_x4_t(bb, bBase + so + (uint32_t)((ks * 16 * PB + np * 16) * 2));
                    #pragma unroll
                    for (int mi = 0; mi < 2; mi++) {
                        #pragma unroll
                        for (int q = 0; q < 2; q++)
                            mma16816(acc[mi][np * 2 + q], a[mi], bb + q * 2);
                    }
                }
            }
            slot = (slot + 1) % 3;
        }

        // ---- epilogue: v[h]*tanh(acc + mc[h]); shfl-reduce over 32 h rows ----
        int hb = h0 + wh * 32;
        float v0 = s_v[hb + g],      m0 = s_mc[hb + g];
        float v1 = s_v[hb + g + 8],  m1 = s_mc[hb + g + 8];
        float v2 = s_v[hb + g + 16], m2 = s_mc[hb + g + 16];
        float v3 = s_v[hb + g + 24], m3 = s_mc[hb + g + 24];
        #pragma unroll
        for (int j = 0; j < 8; j++) {
            #pragma unroll
            for (int p = 0; p < 2; p++) {
                float t = v0 * tanhf(acc[0][j][p]     + m0)
                        + v1 * tanhf(acc[0][j][2 + p] + m1)
                        + v2 * tanhf(acc[1][j][p]     + m2)
                        + v3 * tanhf(acc[1][j][2 + p] + m3);
                t += __shfl_xor_sync(0xffffffffu, t, 4);
                t += __shfl_xor_sync(0xffffffffu, t, 8);
                t += __shfl_xor_sync(0xffffffffu, t, 16);
                if (g == 0)
                    s_part[wh * 128 + wn * 64 + j * 8 + c * 2 + p] += t;
            }
        }
        __syncthreads();   // all MMA/epilogue reads done before next pass prefetch
    }

    if (tid < 128) {
        float s = 0.f;
        #pragma unroll
        for (int ww = 0; ww < 8; ww++) s += s_part[ww * 128 + tid];
        g_scores[b * Nz + n0 + tid] = s;
    }
}

// ============================================================
// Kernel C: row softmax over scores (in-place -> attns)
// ============================================================
__global__ __launch_bounds__(256) void softmax_kernel()
{
    __shared__ float s_red[8];
    int b = blockIdx.x, tid = threadIdx.x;
    int warp = tid >> 5, lane = tid & 31;

    float4 vv = *(const float4*)&g_scores[b * Nz + tid * 4];
    float m = fmaxf(fmaxf(vv.x, vv.y), fmaxf(vv.z, vv.w));
    #pragma unroll
    for (int off = 16; off; off >>= 1)
        m = fmaxf(m, __shfl_xor_sync(0xffffffffu, m, off));
    if (lane == 0) s_red[warp] = m;
    __syncthreads();
    m = s_red[0];
    #pragma unroll
    for (int w = 1; w < 8; w++) m = fmaxf(m, s_red[w]);
    __syncthreads();

    float e0 = expf(vv.x - m), e1 = expf(vv.y - m);
    float e2 = expf(vv.z - m), e3 = expf(vv.w - m);
    float s = e0 + e1 + e2 + e3;
    #pragma unroll
    for (int off = 16; off; off >>= 1)
        s += __shfl_xor_sync(0xffffffffu, s, off);
    if (lane == 0) s_red[warp] = s;
    __syncthreads();
    float tot = 0.f;
    #pragma unroll
    for (int w = 0; w < 8; w++) tot += s_red[w];
    float inv = 1.0f / tot;

    float4 o = make_float4(e0 * inv, e1 * inv, e2 * inv, e3 * inv);
    *(float4*)&g_scores[b * Nz + tid * 4] = o;
}

// ============================================================
// Kernel D: context[b,h] = sum_n attn[b,n]*sn[b,h,n]  (fp16 sn)
// ============================================================
__global__ __launch_bounds__(256) void context_kernel()
{
    __shared__ float s_a[Nz];
    int b = blockIdx.y, h0 = blockIdx.x * 64;
    int tid = threadIdx.x;
    for (int i = tid; i < Nz; i += 256) s_a[i] = g_scores[b * Nz + i];
    __syncthreads();

    int warp = tid >> 5, lane = tid & 31;
    for (int h = h0 + warp; h < h0 + 64; h += 8) {
        const uint4* row = (const uint4*)(g_snh + ((size_t)b * Hz + h) * Nz);
        float a = 0.f;
        #pragma unroll 4
        for (int i = lane; i < Nz / 8; i += 32) {
            uint4 x = row[i];
            const __half2* hp = (const __half2*)&x;
            const float* aw = s_a + i * 8;
            float2 f0 = __half22float2(hp[0]);
            float2 f1 = __half22float2(hp[1]);
            float2 f2 = __half22float2(hp[2]);
            float2 f3 = __half22float2(hp[3]);
            a += f0.x * aw[0] + f0.y * aw[1] + f1.x * aw[2] + f1.y * aw[3]
               + f2.x * aw[4] + f2.y * aw[5] + f3.x * aw[6] + f3.y * aw[7];
        }
        #pragma unroll
        for (int off = 16; off; off >>= 1)
            a += __shfl_xor_sync(0xffffffffu, a, off);
        if (lane == 0) g_context[b * Hz + h] = a;
    }
}

// ============================================================
// Kernel E: out = relu(relu([mc,context]@fc1_W^T + b1)@fc2_W^T + b2)
// ============================================================
__global__ __launch_bounds__(256) void fc_kernel(
    const float* __restrict__ mc,
    const float* __restrict__ fc1W, const float* __restrict__ fc1b,
    const float* __restrict__ fc2W, const float* __restrict__ fc2b)
{
    __shared__ float s_x[4][2 * Hz];
    __shared__ float s_o1[4][Hz];
    int b0 = blockIdx.x * 4;
    int tid = threadIdx.x;

    for (int i = tid; i < 4 * Hz; i += 256) {
        int bb = i >> 9, j = i & 511;
        s_x[bb][j]      = mc[(b0 + bb) * Hz + j];
        s_x[bb][Hz + j] = g_context[(b0 + bb) * Hz + j];
    }
    __syncthreads();

    int warp = tid >> 5, lane = tid & 31;
    for (int h = warp; h < Hz; h += 8) {
        const float* wr = fc1W + h * (2 * Hz);
        float a0 = 0.f, a1 = 0.f, a2 = 0.f, a3 = 0.f;
        for (int k = lane; k < 2 * Hz; k += 32) {
            float w = wr[k];
            a0 += w * s_x[0][k]; a1 += w * s_x[1][k];
            a2 += w * s_x[2][k]; a3 += w * s_x[3][k];
        }
        #pragma unroll
        for (int off = 16; off; off >>= 1) {
            a0 += __shfl_xor_sync(0xffffffffu, a0, off);
            a1 += __shfl_xor_sync(0xffffffffu, a1, off);
            a2 += __shfl_xor_sync(0xffffffffu, a2, off);
            a3 += __shfl_xor_sync(0xffffffffu, a3, off);
        }
        if (lane == 0) {
            float bb = fc1b[h];
            s_o1[0][h] = fmaxf(a0 + bb, 0.f);
            s_o1[1][h] = fmaxf(a1 + bb, 0.f);
            s_o1[2][h] = fmaxf(a2 + bb, 0.f);
            s_o1[3][h] = fmaxf(a3 + bb, 0.f);
        }
    }
    __syncthreads();
    for (int h = warp; h < Hz; h += 8) {
        const float* wr = fc2W + h * Hz;
        float a0 = 0.f, a1 = 0.f, a2 = 0.f, a3 = 0.f;
        for (int k = lane; k < Hz; k += 32) {
            float w = wr[k];
            a0 += w * s_o1[0][k]; a1 += w * s_o1[1][k];
            a2 += w * s_o1[2][k]; a3 += w * s_o1[3][k];
        }
        #pragma unroll
        for (int off = 16; off; off >>= 1) {
            a0 += __shfl_xor_sync(0xffffffffu, a0, off);
            a1 += __shfl_xor_sync(0xffffffffu, a1, off);
            a2 += __shfl_xor_sync(0xffffffffu, a2, off);
            a3 += __shfl_xor_sync(0xffffffffu, a3, off);
        }
        if (lane == 0) {
            float bb = fc2b[h];
            g_out[(b0 + 0) * Hz + h] = fmaxf(a0 + bb, 0.f);
            g_out[(b0 + 1) * Hz + h] = fmaxf(a1 + bb, 0.f);
            g_out[(b0 + 2) * Hz + h] = fmaxf(a2 + bb, 0.f);
            g_out[(b0 + 3) * Hz + h] = fmaxf(a3 + bb, 0.f);
        }
    }
}

// ============================================================
// Kernel F: probs[b,n] = sum_h ptr_v[h]*tanh(sn[b,h,n] + out[b,h])
// fp16 sn; 2 n per thread; ONE tanh.approx.f16x2 per 2 elements.
// 128-thread CTAs, 512 CTAs: fine-grained for SM load balance
// (256 CTAs left ~30% of SMs idle in the tail wave).
// ============================================================
__global__ __launch_bounds__(128) void probs_kernel(
    const float* __restrict__ pv, float* __restrict__ out)
{
    __shared__ float s_o[Hz];
    __shared__ float s_v[Hz];
    int b = blockIdx.y;
    int n0 = blockIdx.x * 256 + threadIdx.x * 2;
    for (int i = threadIdx.x; i < Hz; i += 128) {
        s_o[i] = g_out[b * Hz + i];
        s_v[i] = pv[i];
    }
    __syncthreads();

    const __half* base = g_snh + (size_t)b * Hz * Nz + n0;
    float a0 = 0.f, a1 = 0.f;
    #pragma unroll 8
    for (int h = 0; h < Hz; h++) {
        uint32_t xp = *(const uint32_t*)(base + (size_t)h * Nz);
        float2 x = __half22float2(*(const __half2*)&xp);
        float o = s_o[h], vh = s_v[h];
        uint32_t t = tanh_h2(pack_h2(x.x + o, x.y + o));
        float2 tf = __half22float2(*(__half2*)&t);
        a0 += vh * tf.x;
        a1 += vh * tf.y;
    }
    float2 r = make_float2(a0, a1);
    *(float2*)&out[b * Nz + n0] = r;
}

// ============================================================
extern "C" void kernel_launch(void* const* d_in, const int* in_sizes, int n_in,
                              void* d_out, int out_size)
{
    const float* mc   = (const float*)d_in[0];
    const float* sn   = (const float*)d_in[1];
    const float* attW = (const float*)d_in[2];
    const float* attv = (const float*)d_in[3];
    const float* ptrv = (const float*)d_in[4];
    const float* fc1W = (const float*)d_in[5];
    const float* fc1b = (const float*)d_in[6];
    const float* fc2W = (const float*)d_in[7];
    const float* fc2b = (const float*)d_in[8];
    float* out = (float*)d_out;

    cudaFuncSetAttribute(score_mma_kernel,
                         cudaFuncAttributeMaxDynamicSharedMemorySize, SCORE_SMEM);

    wconv_kernel<<<Hz * Hz / 256, 256>>>(attW);
    snconv_kernel<<<(int)(((size_t)Bz * Hz * Nz / 4) / 256), 256>>>(sn);
    mcproj_kernel<<<Bz / 4, 256>>>(mc, attW);
    score_mma_kernel<<<dim3(8, Bz), 512, SCORE_SMEM>>>(attv);
    softmax_kernel<<<Bz, 256>>>();
    context_kernel<<<dim3(8, Bz), 256>>>();
    fc_kernel<<<Bz / 4, 256>>>(mc, fc1W, fc1b, fc2W, fc2b);
    probs_kernel<<<dim3(Nz / 256, Bz), 128>>>(ptrv, out);
}

// round 17
// speedup vs baseline: 1.4711x; 1.1047x over previous
#include <cuda_runtime.h>
#include <cuda_fp16.h>
#include <cstdint>
#include <math.h>

#define Bz 128
#define Hz 512
#define Nz 1024

// ---------------- scratch (no allocs allowed) ----------------
__device__ float g_mcproj[Bz * Hz];
__device__ float g_scores[Bz * Nz];             // pre-softmax scores
__device__ __half g_Wh[Hz * Hz];                // attn_W[:, :H] fp16
__device__ __half g_snh[(size_t)Bz * Hz * Nz];  // sn fp16 (134MB)

__device__ __forceinline__ uint32_t smem_u32(const void* p) {
    uint32_t a;
    asm("{ .reg .u64 t; cvta.to.shared.u64 t, %1; cvt.u32.u64 %0, t; }"
        : "=r"(a) : "l"(p));
    return a;
}
// HW tanh (MUFU.TANH) f32
__device__ __forceinline__ float tanha(float x) {
    float y;
    asm("tanh.approx.f32 %0, %1;" : "=f"(y) : "f"(x));
    return y;
}
// pack two fp32 -> f16x2 (single cvt op)
__device__ __forceinline__ uint32_t pack_h2(float lo, float hi) {
    uint32_t p;
    asm("cvt.rn.f16x2.f32 %0, %1, %2;" : "=r"(p) : "f"(hi), "f"(lo));
    return p;
}

// ldmatrix x4 (row-major fragments)
__device__ __forceinline__ void ldsm_x4(uint32_t* r, uint32_t addr) {
    asm volatile("ldmatrix.sync.aligned.m8n8.x4.shared.b16 {%0,%1,%2,%3}, [%4];"
                 : "=r"(r[0]), "=r"(r[1]), "=r"(r[2]), "=r"(r[3]) : "r"(addr));
}
// ldmatrix x4 transposed (col-major B fragments)
__device__ __forceinline__ void ldsm_x4_t(uint32_t* r, uint32_t addr) {
    asm volatile("ldmatrix.sync.aligned.m8n8.x4.trans.shared.b16 {%0,%1,%2,%3}, [%4];"
                 : "=r"(r[0]), "=r"(r[1]), "=r"(r[2]), "=r"(r[3]) : "r"(addr));
}
// D += A * B  (m16n8k16, fp16 in, fp32 acc)
__device__ __forceinline__ void mma16816(float* c, const uint32_t* a, const uint32_t* b) {
    asm volatile("mma.sync.aligned.m16n8k16.row.col.f32.f16.f16.f32 "
                 "{%0,%1,%2,%3}, {%4,%5,%6,%7}, {%8,%9}, {%0,%1,%2,%3};"
                 : "+f"(c[0]), "+f"(c[1]), "+f"(c[2]), "+f"(c[3])
                 : "r"(a[0]), "r"(a[1]), "r"(a[2]), "r"(a[3]), "r"(b[0]), "r"(b[1]));
}
__device__ __forceinline__ void cp16(uint32_t dst, const void* src) {
    size_t g = __cvta_generic_to_global(src);
    asm volatile("cp.async.cg.shared.global [%0], [%1], 16;" :: "r"(dst), "l"(g));
}
#define CP_COMMIT() asm volatile("cp.async.commit_group;" ::: "memory")
#define CP_WAIT(n)  asm volatile("cp.async.wait_group %0;" :: "n"(n) : "memory")

// ============================================================
// Kernel P1: convert attn_W[:, :H] to fp16
// ============================================================
__global__ __launch_bounds__(256) void wconv_kernel(const float* __restrict__ W)
{
    int i = blockIdx.x * 256 + threadIdx.x;   // over Hz*Hz
    int h = i >> 9, k = i & 511;
    g_Wh[i] = __float2half_rn(W[h * (2 * Hz) + k]);
}

// ============================================================
// Kernel P2: convert sn to fp16 (linear, float4 per thread)
// ============================================================
__global__ __launch_bounds__(256) void snconv_kernel(const float* __restrict__ sn)
{
    size_t i = (size_t)blockIdx.x * 256 + threadIdx.x;   // over total/4
    float4 x = ((const float4*)sn)[i];
    uint2 o;
    o.x = pack_h2(x.x, x.y);
    o.y = pack_h2(x.z, x.w);
    ((uint2*)g_snh)[i] = o;
}

// ============================================================
// Kernel A: mcproj[b,h] = sum_k attn_W[h, H+k] * mc[b,k]
// ============================================================
__global__ __launch_bounds__(256) void mcproj_kernel(
    const float* __restrict__ mc, const float* __restrict__ W)
{
    __shared__ float s_mc[4][Hz];
    int b0 = blockIdx.x * 4;
    for (int i = threadIdx.x; i < 4 * Hz; i += 256)
        s_mc[i >> 9][i & 511] = mc[(b0 + (i >> 9)) * Hz + (i & 511)];
    __syncthreads();

    int warp = threadIdx.x >> 5, lane = threadIdx.x & 31;
    for (int h = warp; h < Hz; h += 8) {
        const float* wr = W + h * (2 * Hz) + Hz;
        float a0 = 0.f, a1 = 0.f, a2 = 0.f, a3 = 0.f;
        for (int k = lane; k < Hz; k += 32) {
            float w = wr[k];
            a0 += w * s_mc[0][k];
            a1 += w * s_mc[1][k];
            a2 += w * s_mc[2][k];
            a3 += w * s_mc[3][k];
        }
        #pragma unroll
        for (int off = 16; off; off >>= 1) {
            a0 += __shfl_xor_sync(0xffffffffu, a0, off);
            a1 += __shfl_xor_sync(0xffffffffu, a1, off);
            a2 += __shfl_xor_sync(0xffffffffu, a2, off);
            a3 += __shfl_xor_sync(0xffffffffu, a3, off);
        }
        if (lane == 0) {
            g_mcproj[(b0 + 0) * Hz + h] = a0;
            g_mcproj[(b0 + 1) * Hz + h] = a1;
            g_mcproj[(b0 + 2) * Hz + h] = a2;
            g_mcproj[(b0 + 3) * Hz + h] = a3;
        }
    }
}

// ============================================================
// Kernel B (HMMA + 3-stage cp.async): scores[b,n]  — exactly R12
// grid (8 n-strips, 128 b), 512 thr = 16 warps (8h x 2n),
// warp tile 32h x 64n. 2 h-passes of 256h; k in 64-chunks,
// 3 smem slots, 1 sync/chunk. Epilogue tanh via tanhf (FMA pipe).
// ============================================================
static constexpr int PA = 72;    // A pitch (ushorts) = 144B (odd 16B groups)
static constexpr int PB = 136;   // B pitch (ushorts) = 272B (odd 16B groups)
static constexpr int A_SZ = 256 * PA * 2;     // 36864 B (256h x 64k)
static constexpr int B_SZ = 64 * PB * 2;      // 17408 B (64k x 128n)
static constexpr int SLOT_SZ = A_SZ + B_SZ;   // 54272 B
static constexpr int OFF_PART = 3 * SLOT_SZ;              // 162816 (8x128 fl)
static constexpr int OFF_MC   = OFF_PART + 1024 * 4;      // 166912
static constexpr int OFF_V    = OFF_MC + Hz * 4;          // 168960
static constexpr int SCORE_SMEM = OFF_V + Hz * 4;         // 171008

__device__ __forceinline__ void prefetch_chunk(
    uint32_t slotbase, int h0, int k0, int b, int n0, int tid)
{
    // A: 256h x 64k fp16 = 2048 x 16B, 4 per thread
    #pragma unroll
    for (int it = 0; it < 4; it++) {
        int i = tid + it * 512;           // 0..2047
        int h = i >> 3, ch = i & 7;
        uint32_t dst = slotbase + h * (PA * 2) + ch * 16;
        size_t off = (size_t)(h0 + h) * Hz + k0 + ch * 8;
        cp16(dst, g_Wh + off);
    }
    // B: 64k x 128n fp16 = 1024 x 16B, 2 per thread
    uint32_t Bb = slotbase + A_SZ;
    #pragma unroll
    for (int it = 0; it < 2; it++) {
        int i = tid + it * 512;           // 0..1023
        int k = i >> 4, ch = i & 15;
        uint32_t dst = Bb + k * (PB * 2) + ch * 16;
        size_t off = ((size_t)b * Hz + k0 + k) * Nz + n0 + ch * 8;
        cp16(dst, g_snh + off);
    }
}

__global__ __launch_bounds__(512, 1) void score_mma_kernel(const float* __restrict__ v)
{
    extern __shared__ char smem[];
    uint32_t sb = smem_u32(smem);
    int tid = threadIdx.x, w = tid >> 5, lane = tid & 31;
    int wh = w >> 1, wn = w & 1;          // 8 h-warps x 2 n-warps
    int b = blockIdx.y, n0 = blockIdx.x * 128;

    float* s_part = (float*)(smem + OFF_PART);
    float* s_mc   = (float*)(smem + OFF_MC);
    float* s_v    = (float*)(smem + OFF_V);
    for (int i = tid; i < Hz; i += 512) {
        s_mc[i] = g_mcproj[b * Hz + i];
        s_v[i]  = v[i];
    }
    for (int i = tid; i < 1024; i += 512) s_part[i] = 0.f;
    __syncthreads();

    int lrow = lane & 15, lcol8 = (lane >> 4) << 3;
    uint32_t aBase = sb + ((wh * 32 + lrow) * PA + lcol8) * 2;
    uint32_t bBase = sb + A_SZ + (lrow * PB + wn * 64 + lcol8) * 2;
    int g = lane >> 2, c = lane & 3;

    for (int pass = 0; pass < 2; pass++) {
        int h0 = pass * 256;
        float acc[2][8][4];
        #pragma unroll
        for (int mi = 0; mi < 2; mi++)
            #pragma unroll
            for (int j = 0; j < 8; j++)
                #pragma unroll
                for (int r = 0; r < 4; r++) acc[mi][j][r] = 0.f;

        prefetch_chunk(sb + 0 * SLOT_SZ, h0, 0, b, n0, tid);
        CP_COMMIT();
        prefetch_chunk(sb + 1 * SLOT_SZ, h0, 64, b, n0, tid);
        CP_COMMIT();

        int slot = 0;
        for (int kc = 0; kc < 8; kc++) {
            if (kc < 7) { CP_WAIT(1); } else { CP_WAIT(0); }
            __syncthreads();
            if (kc < 6) {
                int ps = (kc + 2) % 3;
                prefetch_chunk(sb + ps * SLOT_SZ, h0, (kc + 2) * 64, b, n0, tid);
                CP_COMMIT();
            }
            uint32_t so = (uint32_t)(slot * SLOT_SZ);
            #pragma unroll
            for (int ks = 0; ks < 4; ks++) {
                uint32_t a[2][4];
                #pragma unroll
                for (int mi = 0; mi < 2; mi++)
                    ldsm_x4(a[mi], aBase + so + (uint32_t)((mi * 16 * PA + ks * 16) * 2));
                #pragma unroll
                for (int np = 0; np < 4; np++) {
                    uint32_t bb[4];
                    ldsm_x4_t(bb, bBase + so + (uint32_t)((ks * 16 * PB + np * 16) * 2));
                    #pragma unroll
                    for (int mi = 0; mi < 2; mi++) {
                        #pragma unroll
                        for (int q = 0; q < 2; q++)
                            mma16816(acc[mi][np * 2 + q], a[mi], bb + q * 2);
                    }
                }
            }
            slot = (slot + 1) % 3;
        }

        // epilogue: v[h]*tanh(acc + mc[h]); shfl-reduce over 32 h rows
        int hb = h0 + wh * 32;
        float v0 = s_v[hb + g],      m0 = s_mc[hb + g];
        float v1 = s_v[hb + g + 8],  m1 = s_mc[hb + g + 8];
        float v2 = s_v[hb + g + 16], m2 = s_mc[hb + g + 16];
        float v3 = s_v[hb + g + 24], m3 = s_mc[hb + g + 24];
        #pragma unroll
        for (int j = 0; j < 8; j++) {
            #pragma unroll
            for (int p = 0; p < 2; p++) {
                float t = v0 * tanhf(acc[0][j][p]     + m0)
                        + v1 * tanhf(acc[0][j][2 + p] + m1)
                        + v2 * tanhf(acc[1][j][p]     + m2)
                        + v3 * tanhf(acc[1][j][2 + p] + m3);
                t += __shfl_xor_sync(0xffffffffu, t, 4);
                t += __shfl_xor_sync(0xffffffffu, t, 8);
                t += __shfl_xor_sync(0xffffffffu, t, 16);
                if (g == 0)
                    s_part[wh * 128 + wn * 64 + j * 8 + c * 2 + p] += t;
            }
        }
        __syncthreads();
    }

    if (tid < 128) {
        float s = 0.f;
        #pragma unroll
        for (int ww = 0; ww < 8; ww++) s += s_part[ww * 128 + tid];
        g_scores[b * Nz + n0 + tid] = s;
    }
}

// ============================================================
// Kernel T (fused tail): softmax -> context -> fc1 -> fc2 -> probs
// grid 128 (one CTA per b), 256 threads. All intermediates in smem.
// Replaces 4 kernels; removes g_context/g_out global round-trips.
// ============================================================
__global__ __launch_bounds__(256) void tail_kernel(
    const float* __restrict__ mc,
    const float* __restrict__ fc1W, const float* __restrict__ fc1b,
    const float* __restrict__ fc2W, const float* __restrict__ fc2b,
    const float* __restrict__ pv,
    float* __restrict__ out)
{
    __shared__ float s_attn[Nz];      // 4KB
    __shared__ float s_x[2 * Hz];     // 4KB: [mc | context]
    __shared__ float s_o1[Hz];        // 2KB
    __shared__ float s_out[Hz];       // 2KB
    __shared__ float s_v[Hz];         // 2KB
    __shared__ float s_red[8];

    int b = blockIdx.x, tid = threadIdx.x;
    int warp = tid >> 5, lane = tid & 31;

    // ---- load mc, ptr_v while doing softmax ----
    for (int i = tid; i < Hz; i += 256) {
        s_x[i] = mc[b * Hz + i];
        s_v[i] = pv[i];
    }

    // ---- softmax over g_scores[b] -> s_attn ----
    float4 vv = *(const float4*)&g_scores[b * Nz + tid * 4];
    float m = fmaxf(fmaxf(vv.x, vv.y), fmaxf(vv.z, vv.w));
    #pragma unroll
    for (int off = 16; off; off >>= 1)
        m = fmaxf(m, __shfl_xor_sync(0xffffffffu, m, off));
    if (lane == 0) s_red[warp] = m;
    __syncthreads();
    m = s_red[0];
    #pragma unroll
    for (int w2 = 1; w2 < 8; w2++) m = fmaxf(m, s_red[w2]);
    __syncthreads();

    float e0 = expf(vv.x - m), e1 = expf(vv.y - m);
    float e2 = expf(vv.z - m), e3 = expf(vv.w - m);
    float s = e0 + e1 + e2 + e3;
    #pragma unroll
    for (int off = 16; off; off >>= 1)
        s += __shfl_xor_sync(0xffffffffu, s, off);
    if (lane == 0) s_red[warp] = s;
    __syncthreads();
    float tot = 0.f;
    #pragma unroll
    for (int w2 = 0; w2 < 8; w2++) tot += s_red[w2];
    float inv = 1.0f / tot;
    *(float4*)&s_attn[tid * 4] = make_float4(e0 * inv, e1 * inv, e2 * inv, e3 * inv);
    __syncthreads();

    // ---- context: s_x[Hz+h] = sum_n attn[n]*sn[b,h,n] (fp16 sn) ----
    for (int h = warp; h < Hz; h += 8) {
        const uint4* row = (const uint4*)(g_snh + ((size_t)b * Hz + h) * Nz);
        float a = 0.f;
        #pragma unroll 4
        for (int i = lane; i < Nz / 8; i += 32) {
            uint4 x = row[i];
            const __half2* hp = (const __half2*)&x;
            const float* aw = s_attn + i * 8;
            float2 f0 = __half22float2(hp[0]);
            float2 f1 = __half22float2(hp[1]);
            float2 f2 = __half22float2(hp[2]);
            float2 f3 = __half22float2(hp[3]);
            a += f0.x * aw[0] + f0.y * aw[1] + f1.x * aw[2] + f1.y * aw[3]
               + f2.x * aw[4] + f2.y * aw[5] + f3.x * aw[6] + f3.y * aw[7];
        }
        #pragma unroll
        for (int off = 16; off; off >>= 1)
            a += __shfl_xor_sync(0xffffffffu, a, off);
        if (lane == 0) s_x[Hz + h] = a;
    }
    __syncthreads();

    // ---- fc1: s_o1[h] = relu(fc1W[h,:] . s_x + b1) ----
    for (int h = warp; h < Hz; h += 8) {
        const float* wr = fc1W + h * (2 * Hz);
        float a = 0.f;
        for (int k = lane; k < 2 * Hz; k += 32)
            a += wr[k] * s_x[k];
        #pragma unroll
        for (int off = 16; off; off >>= 1)
            a += __shfl_xor_sync(0xffffffffu, a, off);
        if (lane == 0) s_o1[h] = fmaxf(a + fc1b[h], 0.f);
    }
    __syncthreads();

    // ---- fc2: s_out[h] = relu(fc2W[h,:] . s_o1 + b2) ----
    for (int h = warp; h < Hz; h += 8) {
        const float* wr = fc2W + h * Hz;
        float a = 0.f;
        for (int k = lane; k < Hz; k += 32)
            a += wr[k] * s_o1[k];
        #pragma unroll
        for (int off = 16; off; off >>= 1)
            a += __shfl_xor_sync(0xffffffffu, a, off);
        if (lane == 0) s_out[h] = fmaxf(a + fc2b[h], 0.f);
    }
    __syncthreads();

    // ---- probs: out[b,n] = sum_h v[h]*tanh(sn[b,h,n] + out[h]) ----
    #pragma unroll
    for (int pass = 0; pass < 2; pass++) {
        int n0 = pass * 512 + tid * 2;
        const __half* base = g_snh + (size_t)b * Hz * Nz + n0;
        float a0 = 0.f, a1 = 0.f;
        #pragma unroll 8
        for (int h = 0; h < Hz; h++) {
            uint32_t xp = *(const uint32_t*)(base + (size_t)h * Nz);
            float2 x = __half22float2(*(const __half2*)&xp);
            float o = s_out[h], vh = s_v[h];
            a0 += vh * tanha(x.x + o);
            a1 += vh * tanha(x.y + o);
        }
        *(float2*)&out[b * Nz + n0] = make_float2(a0, a1);
    }
}

// ============================================================
extern "C" void kernel_launch(void* const* d_in, const int* in_sizes, int n_in,
                              void* d_out, int out_size)
{
    const float* mc   = (const float*)d_in[0];
    const float* sn   = (const float*)d_in[1];
    const float* attW = (const float*)d_in[2];
    const float* attv = (const float*)d_in[3];
    const float* ptrv = (const float*)d_in[4];
    const float* fc1W = (const float*)d_in[5];
    const float* fc1b = (const float*)d_in[6];
    const float* fc2W = (const float*)d_in[7];
    const float* fc2b = (const float*)d_in[8];
    float* out = (float*)d_out;

    cudaFuncSetAttribute(score_mma_kernel,
                         cudaFuncAttributeMaxDynamicSharedMemorySize, SCORE_SMEM);

    wconv_kernel<<<Hz * Hz / 256, 256>>>(attW);
    snconv_kernel<<<(int)(((size_t)Bz * Hz * Nz / 4) / 256), 256>>>(sn);
    mcproj_kernel<<<Bz / 4, 256>>>(mc, attW);
    score_mma_kernel<<<dim3(8, Bz), 512, SCORE_SMEM>>>(attv);
    tail_kernel<<<Bz, 256>>>(mc, fc1W, fc1b, fc2W, fc2b, ptrv, out);
}